// round 13
// baseline (speedup 1.0000x reference)
#include <cuda_runtime.h>
#include <cuda_fp16.h>
#include <math.h>
#include <stdint.h>

#define BB 2048      // batch per domain
#define DD 1024      // feature dim
#define NN 4096      // 2*BB
#define NC 12        // num classes
#define GB 32        // NN / 128 tile grid
#define NBLK (GB * (GB + 1) / 2)   // 528 gemm blocks

// gemm tiling (fp16, 512-thread CTA, 16 warps of 32x32)
#define KT 32                      // K halfs per stage tile (64 B/row)
#define NSTAGE 3
#define RSTRIDE 12                 // uint2 per smem row (8 data + 4 pad) -> LDS.64 conflict-free
#define OPB (128 * RSTRIDE * 8)    // bytes per operand tile (12288)
#define STB (2 * OPB)              // bytes per stage (A+B)
#define SMEM_GEMM (NSTAGE * STB)   // 73728

#define CSB 256                    // colsum partial blocks (SM coverage)

// -------- scratch (static device memory; no allocations allowed) ----------
__device__ __half d_tot[(size_t)NN * DD];     // 8 MB fp16, per-16-K pair-interleaved
__device__ float  d_sq[NN];                   // row squared norms (fp32 originals)
__device__ float  d_colpart[CSB * DD];        // column-sum partials (1 MB)
__device__ float  d_inv_s[NC];
__device__ float  d_inv_t[NC];
__device__ float  d_iv4;                      // 1/(bandwidth*16)
__device__ double d_loss;
__device__ int    d_ticket;

// ------------------------------ PTX helpers -------------------------------
__device__ __forceinline__ uint32_t smem_u32(const void* p) {
    uint32_t a;
    asm("{ .reg .u64 t; cvta.to.shared.u64 t, %1; cvt.u32.u64 %0, t; }" : "=r"(a) : "l"(p));
    return a;
}
__device__ __forceinline__ void cp16(uint32_t dst, const void* src) {
    asm volatile("cp.async.cg.shared.global [%0], [%1], 16;\n" :: "r"(dst), "l"(src));
}
__device__ __forceinline__ void cp_commit() {
    asm volatile("cp.async.commit_group;\n" ::: "memory");
}
template <int N> __device__ __forceinline__ void cp_wait() {
    asm volatile("cp.async.wait_group %0;\n" :: "n"(N) : "memory");
}
// fp16 mma m16n8k16, fp32 accumulate
__device__ __forceinline__ void mma_f16(float* c, const uint32_t* a, const uint32_t* b) {
    asm volatile(
        "mma.sync.aligned.m16n8k16.row.col.f32.f16.f16.f32 "
        "{%0,%1,%2,%3}, {%4,%5,%6,%7}, {%8,%9}, {%0,%1,%2,%3};\n"
        : "+f"(c[0]), "+f"(c[1]), "+f"(c[2]), "+f"(c[3])
        : "r"(a[0]), "r"(a[1]), "r"(a[2]), "r"(a[3]), "r"(b[0]), "r"(b[1]));
}

// ---------------------------------------------------------------------------
// Launch 0: sq[r] = sum(row^2) (fp32); fp16 copy with per-16-K half2 interleave
// [u0,u4,u1,u5,u2,u6,u3,u7] so one LDS.64 = mma fragment (k-lo, k-hi) pair.
__global__ void __launch_bounds__(256) sq_kernel(const float* __restrict__ src,
                                                 const float* __restrict__ tgt) {
    int r = blockIdx.x;
    const float* row = (r < BB) ? src + (size_t)r * DD : tgt + (size_t)(r - BB) * DD;
    int t = threadIdx.x;
    const float4* rf = (const float4*)row;
    float4 v = rf[t];
    float s = v.x * v.x + v.y * v.y + v.z * v.z + v.w * v.w;
    {
        int g16 = t >> 2, j = t & 3;
        const float2* f2 = (const float2*)row;
        float2 lo = f2[g16 * 8 + j];
        float2 hi = f2[g16 * 8 + 4 + j];
        __half2 h0 = __floats2half2_rn(lo.x, lo.y);
        __half2 h1 = __floats2half2_rn(hi.x, hi.y);
        uint2 o;
        o.x = reinterpret_cast<uint32_t&>(h0);
        o.y = reinterpret_cast<uint32_t&>(h1);
        ((uint2*)(d_tot + (size_t)r * DD))[t] = o;
    }
#pragma unroll
    for (int off = 16; off; off >>= 1) s += __shfl_down_sync(0xffffffffu, s, off);
    __shared__ float ws[8];
    if ((t & 31) == 0) ws[t >> 5] = s;
    __syncthreads();
    if (t == 0) {
        float tot = 0.f;
#pragma unroll
        for (int w = 0; w < 8; w++) tot += ws[w];
        d_sq[r] = tot;
    }
}

// ---------------------------------------------------------------------------
// Launch 1: column-sum partials. 256 blocks x 16 rows each (full SM coverage).
__global__ void __launch_bounds__(256) colsum_kernel(const float* __restrict__ src,
                                                     const float* __restrict__ tgt) {
    int b = blockIdx.x, t = threadIdx.x;
    float a0 = 0.f, a1 = 0.f, a2 = 0.f, a3 = 0.f;
    for (int r = 0; r < NN / CSB; r++) {
        int rr = b * (NN / CSB) + r;
        const float* row = (rr < BB) ? src + (size_t)rr * DD : tgt + (size_t)(rr - BB) * DD;
        a0 += row[t];
        a1 += row[t + 256];
        a2 += row[t + 512];
        a3 += row[t + 768];
    }
    d_colpart[b * DD + t]       = a0;
    d_colpart[b * DD + t + 256] = a1;
    d_colpart[b * DD + t + 512] = a2;
    d_colpart[b * DD + t + 768] = a3;
}

// ---------------------------------------------------------------------------
// Launch 2: label class sums + presence -> inverse factors; S1/V2 -> iv4.
__global__ void __launch_bounds__(256) weight_prep_kernel(const float* __restrict__ sl,
                                                          const float* __restrict__ tl) {
    __shared__ float ssum[NC], tsum[NC];
    __shared__ unsigned smask[2];
    __shared__ double red[8];
    int tid = threadIdx.x;
    if (tid < NC) { ssum[tid] = 0.f; tsum[tid] = 0.f; }
    if (tid == 0) { smask[0] = 0u; smask[1] = 0u; d_loss = 0.0; d_ticket = 0; }
    __syncthreads();

    float ls[NC], lt[NC];
#pragma unroll
    for (int c = 0; c < NC; c++) { ls[c] = 0.f; lt[c] = 0.f; }
    unsigned ms = 0u, mt = 0u;
    for (int r = tid; r < BB; r += 256) {
        float smax = -1e30f, tmax = -1e30f;
        int sa = 0, ta = 0;
#pragma unroll
        for (int c = 0; c < NC; c++) {
            float sv = sl[r * NC + c], tv = tl[r * NC + c];
            ls[c] += sv;  lt[c] += tv;
            if (sv > smax) { smax = sv; sa = c; }
            if (tv > tmax) { tmax = tv; ta = c; }
        }
        ms |= 1u << sa;  mt |= 1u << ta;
    }
#pragma unroll
    for (int off = 16; off; off >>= 1) {
#pragma unroll
        for (int c = 0; c < NC; c++) {
            ls[c] += __shfl_down_sync(0xffffffffu, ls[c], off);
            lt[c] += __shfl_down_sync(0xffffffffu, lt[c], off);
        }
        ms |= __shfl_down_sync(0xffffffffu, ms, off);
        mt |= __shfl_down_sync(0xffffffffu, mt, off);
    }
    if ((tid & 31) == 0) {
#pragma unroll
        for (int c = 0; c < NC; c++) {
            atomicAdd(&ssum[c], ls[c]);
            atomicAdd(&tsum[c], lt[c]);
        }
        atomicOr(&smask[0], ms);
        atomicOr(&smask[1], mt);
    }
    __syncthreads();
    if (tid < NC) {
        bool common = ((smask[0] >> tid) & 1u) && ((smask[1] >> tid) & 1u);
        d_inv_s[tid] = (common && ssum[tid] > 0.f) ? 1.f / ssum[tid] : 0.f;
        d_inv_t[tid] = (common && tsum[tid] > 0.f) ? 1.f / tsum[tid] : 0.f;
    }

    // ---- S1 = sum(d_sq) ----
    double s1 = 0.0;
    for (int r = tid; r < NN; r += 256) s1 += (double)d_sq[r];
#pragma unroll
    for (int off = 16; off; off >>= 1) s1 += __shfl_down_sync(0xffffffffu, s1, off);
    if ((tid & 31) == 0) red[tid >> 5] = s1;
    __syncthreads();

    // ---- V2 = sum over columns of (colsum)^2 ----
    double v2 = 0.0;
    for (int c = tid; c < DD; c += 256) {
        float cs0 = 0.f;
        double cs = 0.0;
#pragma unroll 8
        for (int b = 0; b < CSB; b++) {
            cs0 += d_colpart[b * DD + c];
            if ((b & 31) == 31) { cs += (double)cs0; cs0 = 0.f; }
        }
        v2 += cs * cs;
    }
#pragma unroll
    for (int off = 16; off; off >>= 1) v2 += __shfl_down_sync(0xffffffffu, v2, off);
    __shared__ double red2[8];
    if ((tid & 31) == 0) red2[tid >> 5] = v2;
    __syncthreads();

    if (tid == 0) {
        double S1 = 0.0, V2 = 0.0;
#pragma unroll
        for (int w = 0; w < 8; w++) { S1 += red[w]; V2 += red2[w]; }
        double n = (double)NN;
        double sum_l2 = 2.0 * n * S1 - 2.0 * V2;      // analytic sum of pairwise sq dists
        double bw = sum_l2 / (n * n - n) / 4.0;       // / KERNEL_MUL^(KERNEL_NUM//2)
        d_iv4 = (float)(1.0 / (bw * 16.0));           // bw==0 -> inf -> NaN path
    }
}

// ---------------------------------------------------------------------------
// Launch 3 (PROFILED): fused FP16 Gram GEMM + LMMD loss. 512 threads,
// 16 warps of 32x32 (acc 32 regs) -> 2 CTAs/SM = 32 warps/SM.
__device__ __forceinline__ void load_stage(uint32_t sbase, const __half* Ab, const __half* Bb,
                                           int ktile, int tid) {
    int kbyte = ktile * (KT * 2);      // 64 bytes per row per tile
    int r = tid >> 2;                  // row 0..127 (512 threads = 512 chunks)
    int c = (tid & 3) << 4;            // byte col 0/16/32/48
    uint32_t d = sbase + (uint32_t)(r * (RSTRIDE * 8) + c);
    cp16(d,       (const char*)Ab + (size_t)r * (DD * 2) + kbyte + c);
    cp16(d + OPB, (const char*)Bb + (size_t)r * (DD * 2) + kbyte + c);
}

__global__ void __launch_bounds__(512, 2) gemm_loss_kernel(const float* __restrict__ sl,
                                                           const float* __restrict__ tl,
                                                           float* __restrict__ out) {
    extern __shared__ __align__(16) char sm[];
    uint32_t sb = smem_u32(sm);

    int b = blockIdx.x, bi = 0, rem = b;
    while (rem >= GB - bi) { rem -= GB - bi; bi++; }
    int bj = bi + rem;
    int i0 = bi * 128, j0 = bj * 128;
    const __half* Ab = d_tot + (size_t)i0 * DD;
    const __half* Bb = d_tot + (size_t)j0 * DD;

    int tid  = threadIdx.x;
    int lane = tid & 31;
    int wid  = tid >> 5;          // 0..15
    int wm   = wid >> 2;          // 0..3 (32 rows each)
    int wn   = wid & 3;           // 0..3 (32 cols each)
    int g    = lane >> 2;
    int tg   = lane & 3;

    float acc[2][4][4];
#pragma unroll
    for (int mt = 0; mt < 2; mt++)
#pragma unroll
        for (int nt = 0; nt < 4; nt++)
#pragma unroll
            for (int f = 0; f < 4; f++) acc[mt][nt][f] = 0.f;

    const int NTILES = DD / KT;    // 32

    load_stage(sb + 0 * STB, Ab, Bb, 0, tid); cp_commit();
    load_stage(sb + 1 * STB, Ab, Bb, 1, tid); cp_commit();

    int s = 0;
    for (int t = 0; t < NTILES; t++) {
        if (t < NTILES - 1) cp_wait<1>(); else cp_wait<0>();
        __syncthreads();

        const uint2* A2 = (const uint2*)(sm + s * STB);
        const uint2* B2 = (const uint2*)(sm + s * STB + OPB);
#pragma unroll
        for (int ksg = 0; ksg < 2; ksg++) {        // two k16 groups per stage
            uint32_t af[2][4], bf[4][2];
#pragma unroll
            for (int mt = 0; mt < 2; mt++) {
                int ar = wm * 32 + mt * 16 + g;
                uint2 p0 = A2[ar * RSTRIDE + ksg * 4 + tg];        // row g:   (k-lo, k-hi)
                uint2 p1 = A2[(ar + 8) * RSTRIDE + ksg * 4 + tg];  // row g+8
                af[mt][0] = p0.x;  af[mt][1] = p1.x;
                af[mt][2] = p0.y;  af[mt][3] = p1.y;
            }
#pragma unroll
            for (int nt = 0; nt < 4; nt++) {
                int br = wn * 32 + nt * 8 + g;
                uint2 pb = B2[br * RSTRIDE + ksg * 4 + tg];
                bf[nt][0] = pb.x;  bf[nt][1] = pb.y;
            }
#pragma unroll
            for (int mt = 0; mt < 2; mt++)
#pragma unroll
                for (int nt = 0; nt < 4; nt++)
                    mma_f16(acc[mt][nt], af[mt], bf[nt]);
        }

        if (t + 2 < NTILES) {
            int ns = (s + 2) % NSTAGE;
            load_stage(sb + ns * STB, Ab, Bb, t + 2, tid);
            cp_commit();
        }
        s = (s + 1) % NSTAGE;
    }

    // ---------------- fused loss epilogue ----------------
    float* rowlab = (float*)sm;              // [128][12]
    float* collab = (float*)(sm + 6144);     // [128][12]
    __syncthreads();                         // all mainloop smem reads done
    {
        bool rowS = (bi < 16), colS = (bj < 16);
        const float* rl = rowS ? sl : tl;
        const float* cl = colS ? sl : tl;
        const float* ri = rowS ? d_inv_s : d_inv_t;
        const float* ci = colS ? d_inv_s : d_inv_t;
        int ro = rowS ? i0 : i0 - BB;
        int co = colS ? j0 : j0 - BB;
        for (int e = tid; e < 128 * NC; e += 512) {
            int r = e / NC, c = e % NC;
            rowlab[e] = rl[(ro + r) * NC + c] * ri[c];
            collab[e] = cl[(co + r) * NC + c] * ci[c];
        }
    }
    __syncthreads();

    float iv4 = d_iv4;
    float part = 0.f;
#pragma unroll
    for (int mt = 0; mt < 2; mt++) {
        int ra = wm * 32 + mt * 16 + g;
        float sqa0 = d_sq[i0 + ra], sqa1 = d_sq[i0 + ra + 8];
        const float* r0 = rowlab + ra * NC;
        const float* r1 = rowlab + (ra + 8) * NC;
#pragma unroll
        for (int nt = 0; nt < 4; nt++) {
            int ca = wn * 32 + nt * 8 + 2 * tg;
            float sqb0 = d_sq[j0 + ca], sqb1 = d_sq[j0 + ca + 1];
            const float* c0 = collab + ca * NC;
            const float* c1 = collab + (ca + 1) * NC;

            float w00 = 0.f, w01 = 0.f, w10 = 0.f, w11 = 0.f;
#pragma unroll
            for (int c = 0; c < NC; c++) {
                float rr0 = r0[c], rr1 = r1[c];
                float cc0 = c0[c], cc1 = c1[c];
                w00 = fmaf(rr0, cc0, w00);
                w01 = fmaf(rr0, cc1, w01);
                w10 = fmaf(rr1, cc0, w10);
                w11 = fmaf(rr1, cc1, w11);
            }

            float v0 = fmaxf(sqa0 + sqb0 - 2.f * acc[mt][nt][0], 0.f);
            float v1 = fmaxf(sqa0 + sqb1 - 2.f * acc[mt][nt][1], 0.f);
            float v2 = fmaxf(sqa1 + sqb0 - 2.f * acc[mt][nt][2], 0.f);
            float v3 = fmaxf(sqa1 + sqb1 - 2.f * acc[mt][nt][3], 0.f);

            float e0 = __expf(-v0 * iv4), e1 = __expf(-v1 * iv4);
            float e2 = __expf(-v2 * iv4), e3 = __expf(-v3 * iv4);
            float p0 = e0 * e0, p1 = e1 * e1, p2 = e2 * e2, p3 = e3 * e3;
            float k0 = e0 + p0, k1 = e1 + p1, k2 = e2 + p2, k3 = e3 + p3;
            p0 *= p0; p1 *= p1; p2 *= p2; p3 *= p3;     // e^4
            k0 += p0; k1 += p1; k2 += p2; k3 += p3;
            p0 *= p0; p1 *= p1; p2 *= p2; p3 *= p3;     // e^8
            k0 += p0; k1 += p1; k2 += p2; k3 += p3;
            p0 *= p0; p1 *= p1; p2 *= p2; p3 *= p3;     // e^16
            k0 += p0; k1 += p1; k2 += p2; k3 += p3;

            part += w00 * k0 + w01 * k1 + w10 * k2 + w11 * k3;
        }
    }
    float factor = ((bi < 16) == (bj < 16)) ? ((bi == bj) ? 1.f : 2.f) : -2.f;
    part *= factor * (1.f / 12.f);

#pragma unroll
    for (int off = 16; off; off >>= 1) part += __shfl_down_sync(0xffffffffu, part, off);
    __shared__ double wsum[16];
    if (lane == 0) wsum[wid] = (double)part;
    __syncthreads();
    if (tid == 0) {
        double tot = 0.0;
#pragma unroll
        for (int w = 0; w < 16; w++) tot += wsum[w];
        atomicAdd(&d_loss, tot);
        __threadfence();
        int old = atomicAdd(&d_ticket, 1);
        if (old == NBLK - 1) {                     // last CTA: finalize
            double v = *((volatile double*)&d_loss);
            out[0] = isnan(v) ? 0.f : (float)v;
        }
    }
}

// ---------------------------------------------------------------------------
extern "C" void kernel_launch(void* const* d_in, const int* in_sizes, int n_in,
                              void* d_out, int out_size) {
    const float* src = (const float*)d_in[0];
    const float* tgt = (const float*)d_in[1];
    const float* sl  = (const float*)d_in[2];
    const float* tl  = (const float*)d_in[3];
    float* out = (float*)d_out;

    cudaFuncSetAttribute(gemm_loss_kernel, cudaFuncAttributeMaxDynamicSharedMemorySize, SMEM_GEMM);

    sq_kernel<<<NN, 256>>>(src, tgt);                                    // 0
    colsum_kernel<<<CSB, 256>>>(src, tgt);                               // 1
    weight_prep_kernel<<<1, 256>>>(sl, tl);                              // 2
    gemm_loss_kernel<<<NBLK, 512, SMEM_GEMM>>>(sl, tl, out);             // 3 (profiled)
}

// round 14
// speedup vs baseline: 1.4339x; 1.4339x over previous
#include <cuda_runtime.h>
#include <cuda_fp16.h>
#include <math.h>
#include <stdint.h>

#define BB 2048      // batch per domain
#define DD 1024      // feature dim
#define NN 4096      // 2*BB
#define NC 12        // num classes
#define GB 32        // NN / 128 tile grid
#define NBLK (GB * (GB + 1) / 2)   // 528 gemm blocks

// gemm tiling (fp16, 256-thread CTA, 8 warps of 64x32, ldmatrix fragments)
#define KT 32                      // K halfs per stage tile (64 B/row)
#define NSTAGE 3
#define RBYTES 80                  // bytes per smem row (64 data + 16 pad) -> ldmatrix conflict-free
#define OPB (128 * RBYTES)         // bytes per operand tile (10240)
#define STB (2 * OPB)              // bytes per stage (A+B)
#define SMEM_GEMM (NSTAGE * STB)   // 61440

#define CSB 32                     // colsum partial blocks (R11 config)

// -------- scratch (static device memory; no allocations allowed) ----------
__device__ __half d_tot[(size_t)NN * DD];     // 8 MB fp16, plain row-major
__device__ float  d_sq[NN];                   // row squared norms (fp32 originals)
__device__ float  d_colpart[CSB * DD];        // column-sum partials
__device__ float  d_inv_s[NC];
__device__ float  d_inv_t[NC];
__device__ float  d_iv4;                      // 1/(bandwidth*16)
__device__ double d_loss;
__device__ int    d_ticket;

// ------------------------------ PTX helpers -------------------------------
__device__ __forceinline__ uint32_t smem_u32(const void* p) {
    uint32_t a;
    asm("{ .reg .u64 t; cvta.to.shared.u64 t, %1; cvt.u32.u64 %0, t; }" : "=r"(a) : "l"(p));
    return a;
}
__device__ __forceinline__ void cp16(uint32_t dst, const void* src) {
    asm volatile("cp.async.cg.shared.global [%0], [%1], 16;\n" :: "r"(dst), "l"(src));
}
__device__ __forceinline__ void cp_commit() {
    asm volatile("cp.async.commit_group;\n" ::: "memory");
}
template <int N> __device__ __forceinline__ void cp_wait() {
    asm volatile("cp.async.wait_group %0;\n" :: "n"(N) : "memory");
}
__device__ __forceinline__ void ldmx4(uint32_t* r, uint32_t addr) {
    asm volatile("ldmatrix.sync.aligned.m8n8.x4.shared.b16 {%0,%1,%2,%3}, [%4];"
                 : "=r"(r[0]), "=r"(r[1]), "=r"(r[2]), "=r"(r[3]) : "r"(addr));
}
// fp16 mma m16n8k16, fp32 accumulate
__device__ __forceinline__ void mma_f16(float* c, const uint32_t* a, const uint32_t* b) {
    asm volatile(
        "mma.sync.aligned.m16n8k16.row.col.f32.f16.f16.f32 "
        "{%0,%1,%2,%3}, {%4,%5,%6,%7}, {%8,%9}, {%0,%1,%2,%3};\n"
        : "+f"(c[0]), "+f"(c[1]), "+f"(c[2]), "+f"(c[3])
        : "r"(a[0]), "r"(a[1]), "r"(a[2]), "r"(a[3]), "r"(b[0]), "r"(b[1]));
}

// ---------------------------------------------------------------------------
// Launch 0: sq[r] = sum(row^2) (fp32); plain fp16 copy (k-contiguous).
__global__ void __launch_bounds__(256) sq_kernel(const float* __restrict__ src,
                                                 const float* __restrict__ tgt) {
    int r = blockIdx.x;
    const float* row = (r < BB) ? src + (size_t)r * DD : tgt + (size_t)(r - BB) * DD;
    int t = threadIdx.x;
    float4 v = ((const float4*)row)[t];
    float s = v.x * v.x + v.y * v.y + v.z * v.z + v.w * v.w;
    {
        __half2 h0 = __floats2half2_rn(v.x, v.y);
        __half2 h1 = __floats2half2_rn(v.z, v.w);
        uint2 o;
        o.x = reinterpret_cast<uint32_t&>(h0);
        o.y = reinterpret_cast<uint32_t&>(h1);
        ((uint2*)(d_tot + (size_t)r * DD))[t] = o;
    }
#pragma unroll
    for (int off = 16; off; off >>= 1) s += __shfl_down_sync(0xffffffffu, s, off);
    __shared__ float ws[8];
    if ((t & 31) == 0) ws[t >> 5] = s;
    __syncthreads();
    if (t == 0) {
        float tot = 0.f;
#pragma unroll
        for (int w = 0; w < 8; w++) tot += ws[w];
        d_sq[r] = tot;
    }
}

// ---------------------------------------------------------------------------
// Launch 1: column-sum partials. Block b owns 128 rows.
__global__ void __launch_bounds__(256) colsum_kernel(const float* __restrict__ src,
                                                     const float* __restrict__ tgt) {
    int b = blockIdx.x, t = threadIdx.x;
    float a0 = 0.f, a1 = 0.f, a2 = 0.f, a3 = 0.f;
    for (int r = 0; r < NN / CSB; r++) {
        int rr = b * (NN / CSB) + r;
        const float* row = (rr < BB) ? src + (size_t)rr * DD : tgt + (size_t)(rr - BB) * DD;
        a0 += row[t];
        a1 += row[t + 256];
        a2 += row[t + 512];
        a3 += row[t + 768];
    }
    d_colpart[b * DD + t]       = a0;
    d_colpart[b * DD + t + 256] = a1;
    d_colpart[b * DD + t + 512] = a2;
    d_colpart[b * DD + t + 768] = a3;
}

// ---------------------------------------------------------------------------
// Launch 2: label class sums + presence -> inverse factors; S1/V2 -> iv4.
__global__ void __launch_bounds__(256) weight_prep_kernel(const float* __restrict__ sl,
                                                          const float* __restrict__ tl) {
    __shared__ float ssum[NC], tsum[NC];
    __shared__ unsigned smask[2];
    __shared__ double red[8];
    int tid = threadIdx.x;
    if (tid < NC) { ssum[tid] = 0.f; tsum[tid] = 0.f; }
    if (tid == 0) { smask[0] = 0u; smask[1] = 0u; d_loss = 0.0; d_ticket = 0; }
    __syncthreads();

    float ls[NC], lt[NC];
#pragma unroll
    for (int c = 0; c < NC; c++) { ls[c] = 0.f; lt[c] = 0.f; }
    unsigned ms = 0u, mt = 0u;
    for (int r = tid; r < BB; r += 256) {
        float smax = -1e30f, tmax = -1e30f;
        int sa = 0, ta = 0;
#pragma unroll
        for (int c = 0; c < NC; c++) {
            float sv = sl[r * NC + c], tv = tl[r * NC + c];
            ls[c] += sv;  lt[c] += tv;
            if (sv > smax) { smax = sv; sa = c; }
            if (tv > tmax) { tmax = tv; ta = c; }
        }
        ms |= 1u << sa;  mt |= 1u << ta;
    }
#pragma unroll
    for (int off = 16; off; off >>= 1) {
#pragma unroll
        for (int c = 0; c < NC; c++) {
            ls[c] += __shfl_down_sync(0xffffffffu, ls[c], off);
            lt[c] += __shfl_down_sync(0xffffffffu, lt[c], off);
        }
        ms |= __shfl_down_sync(0xffffffffu, ms, off);
        mt |= __shfl_down_sync(0xffffffffu, mt, off);
    }
    if ((tid & 31) == 0) {
#pragma unroll
        for (int c = 0; c < NC; c++) {
            atomicAdd(&ssum[c], ls[c]);
            atomicAdd(&tsum[c], lt[c]);
        }
        atomicOr(&smask[0], ms);
        atomicOr(&smask[1], mt);
    }
    __syncthreads();
    if (tid < NC) {
        bool common = ((smask[0] >> tid) & 1u) && ((smask[1] >> tid) & 1u);
        d_inv_s[tid] = (common && ssum[tid] > 0.f) ? 1.f / ssum[tid] : 0.f;
        d_inv_t[tid] = (common && tsum[tid] > 0.f) ? 1.f / tsum[tid] : 0.f;
    }

    // ---- S1 = sum(d_sq) ----
    double s1 = 0.0;
    for (int r = tid; r < NN; r += 256) s1 += (double)d_sq[r];
#pragma unroll
    for (int off = 16; off; off >>= 1) s1 += __shfl_down_sync(0xffffffffu, s1, off);
    if ((tid & 31) == 0) red[tid >> 5] = s1;
    __syncthreads();

    // ---- V2 = sum over columns of (colsum)^2 ----
    double v2 = 0.0;
    for (int c = tid; c < DD; c += 256) {
        double cs = 0.0;
#pragma unroll 4
        for (int b = 0; b < CSB; b++) cs += (double)d_colpart[b * DD + c];
        v2 += cs * cs;
    }
#pragma unroll
    for (int off = 16; off; off >>= 1) v2 += __shfl_down_sync(0xffffffffu, v2, off);
    __shared__ double red2[8];
    if ((tid & 31) == 0) red2[tid >> 5] = v2;
    __syncthreads();

    if (tid == 0) {
        double S1 = 0.0, V2 = 0.0;
#pragma unroll
        for (int w = 0; w < 8; w++) { S1 += red[w]; V2 += red2[w]; }
        double n = (double)NN;
        double sum_l2 = 2.0 * n * S1 - 2.0 * V2;      // analytic sum of pairwise sq dists
        double bw = sum_l2 / (n * n - n) / 4.0;       // / KERNEL_MUL^(KERNEL_NUM//2)
        d_iv4 = (float)(1.0 / (bw * 16.0));           // bw==0 -> inf -> NaN path
    }
}

// ---------------------------------------------------------------------------
// Launch 3 (PROFILED): fused FP16 Gram GEMM + LMMD loss. 256 threads,
// 8 warps of 64x32, ldmatrix fragment loads.
__device__ __forceinline__ void load_stage(uint32_t sbase, const __half* Ab, const __half* Bb,
                                           int ktile, int tid) {
    int kbyte = ktile * (KT * 2);      // 64 bytes per row per tile
#pragma unroll
    for (int i = 0; i < 2; i++) {
        int u = tid + (i << 8);        // 0..511 chunk id
        int r = u >> 2;                // row 0..127
        int c = (u & 3) << 4;          // byte col 0/16/32/48
        uint32_t d = sbase + (uint32_t)(r * RBYTES + c);
        cp16(d,       (const char*)Ab + (size_t)r * (DD * 2) + kbyte + c);
        cp16(d + OPB, (const char*)Bb + (size_t)r * (DD * 2) + kbyte + c);
    }
}

__global__ void __launch_bounds__(256, 2) gemm_loss_kernel(const float* __restrict__ sl,
                                                           const float* __restrict__ tl,
                                                           float* __restrict__ out) {
    extern __shared__ __align__(16) char sm[];
    uint32_t sb = smem_u32(sm);

    int b = blockIdx.x, bi = 0, rem = b;
    while (rem >= GB - bi) { rem -= GB - bi; bi++; }
    int bj = bi + rem;
    int i0 = bi * 128, j0 = bj * 128;
    const __half* Ab = d_tot + (size_t)i0 * DD;
    const __half* Bb = d_tot + (size_t)j0 * DD;

    int tid  = threadIdx.x;
    int lane = tid & 31;
    int wid  = tid >> 5;
    int wm   = wid >> 2;          // warp row (64 rows)
    int wn   = wid & 3;           // warp col (32 cols)
    int g    = lane >> 2;
    int tg   = lane & 3;

    // ldmatrix lane -> row-within-quad mapping (tile = lane>>3, l8 = lane&7)
    int ltile = lane >> 3;        // 0..3
    int l8    = lane & 7;         // 0..7

    float acc[4][4][4];
#pragma unroll
    for (int mt = 0; mt < 4; mt++)
#pragma unroll
        for (int nt = 0; nt < 4; nt++)
#pragma unroll
            for (int f = 0; f < 4; f++) acc[mt][nt][f] = 0.f;

    const int NTILES = DD / KT;    // 32

    load_stage(sb + 0 * STB, Ab, Bb, 0, tid); cp_commit();
    load_stage(sb + 1 * STB, Ab, Bb, 1, tid); cp_commit();

    int s = 0;
    for (int t = 0; t < NTILES; t++) {
        if (t < NTILES - 1) cp_wait<1>(); else cp_wait<0>();
        __syncthreads();

        uint32_t Abase = sb + s * STB;
        uint32_t Bbase = Abase + OPB;
#pragma unroll
        for (int ksg = 0; ksg < 2; ksg++) {        // two k16 groups per stage
            int kb = ksg * 32;                     // byte offset of k-group
            uint32_t af[4][4], bf[2][4];
            // A: 4 tiles of 16x16. x4 tile order: (r0-7 klo),(r8-15 klo),(r0-7 khi),(r8-15 khi)
#pragma unroll
            for (int mt = 0; mt < 4; mt++) {
                int ar = wm * 64 + mt * 16 + (ltile & 1) * 8 + l8;
                uint32_t addr = Abase + ar * RBYTES + kb + (ltile >> 1) * 16;
                ldmx4(af[mt], addr);
            }
            // B: 2 x4 loads, each covering nt pair: (n0-7 klo),(n0-7 khi),(n8-15 klo),(n8-15 khi)
#pragma unroll
            for (int np = 0; np < 2; np++) {
                int br = wn * 32 + np * 16 + (ltile >> 1) * 8 + l8;
                uint32_t addr = Bbase + br * RBYTES + kb + (ltile & 1) * 16;
                ldmx4(bf[np], addr);
            }
#pragma unroll
            for (int mt = 0; mt < 4; mt++)
#pragma unroll
                for (int nt = 0; nt < 4; nt++)
                    mma_f16(acc[mt][nt], af[mt], &bf[nt >> 1][(nt & 1) * 2]);
        }

        if (t + 2 < NTILES) {
            int ns = (s + 2) % NSTAGE;
            load_stage(sb + ns * STB, Ab, Bb, t + 2, tid);
            cp_commit();
        }
        s = (s + 1) % NSTAGE;
    }

    // ---------------- fused loss epilogue ----------------
    float* rowlab = (float*)sm;              // [128][12]
    float* collab = (float*)(sm + 6144);     // [128][12]
    __syncthreads();                         // all mainloop smem reads done
    {
        bool rowS = (bi < 16), colS = (bj < 16);
        const float* rl = rowS ? sl : tl;
        const float* cl = colS ? sl : tl;
        const float* ri = rowS ? d_inv_s : d_inv_t;
        const float* ci = colS ? d_inv_s : d_inv_t;
        int ro = rowS ? i0 : i0 - BB;
        int co = colS ? j0 : j0 - BB;
        for (int e = tid; e < 128 * NC; e += 256) {
            int r = e / NC, c = e % NC;
            rowlab[e] = rl[(ro + r) * NC + c] * ri[c];
            collab[e] = cl[(co + r) * NC + c] * ci[c];
        }
    }
    __syncthreads();

    float iv4 = d_iv4;
    float part = 0.f;
#pragma unroll
    for (int mt = 0; mt < 4; mt++) {
        int ra = wm * 64 + mt * 16 + g;
        float sqa0 = d_sq[i0 + ra], sqa1 = d_sq[i0 + ra + 8];
        const float* r0 = rowlab + ra * NC;
        const float* r1 = rowlab + (ra + 8) * NC;
#pragma unroll
        for (int nt = 0; nt < 4; nt++) {
            int ca = wn * 32 + nt * 8 + 2 * tg;
            float sqb0 = d_sq[j0 + ca], sqb1 = d_sq[j0 + ca + 1];
            const float* c0 = collab + ca * NC;
            const float* c1 = collab + (ca + 1) * NC;

            float w00 = 0.f, w01 = 0.f, w10 = 0.f, w11 = 0.f;
#pragma unroll
            for (int c = 0; c < NC; c++) {
                float rr0 = r0[c], rr1 = r1[c];
                float cc0 = c0[c], cc1 = c1[c];
                w00 = fmaf(rr0, cc0, w00);
                w01 = fmaf(rr0, cc1, w01);
                w10 = fmaf(rr1, cc0, w10);
                w11 = fmaf(rr1, cc1, w11);
            }

            float v0 = fmaxf(sqa0 + sqb0 - 2.f * acc[mt][nt][0], 0.f);
            float v1 = fmaxf(sqa0 + sqb1 - 2.f * acc[mt][nt][1], 0.f);
            float v2 = fmaxf(sqa1 + sqb0 - 2.f * acc[mt][nt][2], 0.f);
            float v3 = fmaxf(sqa1 + sqb1 - 2.f * acc[mt][nt][3], 0.f);

            float e0 = __expf(-v0 * iv4), e1 = __expf(-v1 * iv4);
            float e2 = __expf(-v2 * iv4), e3 = __expf(-v3 * iv4);
            float p0 = e0 * e0, p1 = e1 * e1, p2 = e2 * e2, p3 = e3 * e3;
            float k0 = e0 + p0, k1 = e1 + p1, k2 = e2 + p2, k3 = e3 + p3;
            p0 *= p0; p1 *= p1; p2 *= p2; p3 *= p3;     // e^4
            k0 += p0; k1 += p1; k2 += p2; k3 += p3;
            p0 *= p0; p1 *= p1; p2 *= p2; p3 *= p3;     // e^8
            k0 += p0; k1 += p1; k2 += p2; k3 += p3;
            p0 *= p0; p1 *= p1; p2 *= p2; p3 *= p3;     // e^16
            k0 += p0; k1 += p1; k2 += p2; k3 += p3;

            part += w00 * k0 + w01 * k1 + w10 * k2 + w11 * k3;
        }
    }
    float factor = ((bi < 16) == (bj < 16)) ? ((bi == bj) ? 1.f : 2.f) : -2.f;
    part *= factor * (1.f / 12.f);

#pragma unroll
    for (int off = 16; off; off >>= 1) part += __shfl_down_sync(0xffffffffu, part, off);
    __shared__ double wsum[8];
    if (lane == 0) wsum[wid] = (double)part;
    __syncthreads();
    if (tid == 0) {
        double tot = 0.0;
#pragma unroll
        for (int w = 0; w < 8; w++) tot += wsum[w];
        atomicAdd(&d_loss, tot);
        __threadfence();
        int old = atomicAdd(&d_ticket, 1);
        if (old == NBLK - 1) {                     // last CTA: finalize
            double v = *((volatile double*)&d_loss);
            out[0] = isnan(v) ? 0.f : (float)v;
        }
    }
}

// ---------------------------------------------------------------------------
extern "C" void kernel_launch(void* const* d_in, const int* in_sizes, int n_in,
                              void* d_out, int out_size) {
    const float* src = (const float*)d_in[0];
    const float* tgt = (const float*)d_in[1];
    const float* sl  = (const float*)d_in[2];
    const float* tl  = (const float*)d_in[3];
    float* out = (float*)d_out;

    cudaFuncSetAttribute(gemm_loss_kernel, cudaFuncAttributeMaxDynamicSharedMemorySize, SMEM_GEMM);

    sq_kernel<<<NN, 256>>>(src, tgt);                                    // 0
    colsum_kernel<<<CSB, 256>>>(src, tgt);                               // 1
    weight_prep_kernel<<<1, 256>>>(sl, tl);                              // 2
    gemm_loss_kernel<<<NBLK, 256, SMEM_GEMM>>>(sl, tl, out);             // 3 (profiled)
}